// round 6
// baseline (speedup 1.0000x reference)
#include <cuda_runtime.h>
#include <cuda_bf16.h>
#include <cstdint>

// Conv2d 3x3 VALID, C_in=C_out=8, 2048x2048 fp32 -> (8, 2046, 2046)
// Round 6: mma.sync m16n8k16 bf16 hi/lo conv, 2 output rows per warp to
// reuse A fragments across overlapping ky taps (LDS bytes cut 1.5x).

#define CIN   8
#define COUT  8
#define IH    2048
#define IW    2048
#define OHH   2046
#define OWW   2046
#define CH    (IH*IW)
#define TPX   128
#define TR    8           // output rows per block (2 per warp)
#define INR   10          // TR + 2 input rows staged
#define INPX  130

typedef uint32_t u32;

__device__ __forceinline__ u32 bf16_hi_lo_pack(float v) {
    __nv_bfloat16 hb = __float2bfloat16(v);
    float hf = __bfloat162float(hb);
    __nv_bfloat16 lb = __float2bfloat16(v - hf);
    return (u32)__bfloat16_as_ushort(hb) | ((u32)__bfloat16_as_ushort(lb) << 16);
}

__device__ __forceinline__ void mma16816(float* d,
                                         u32 a0, u32 a1, u32 a2, u32 a3,
                                         u32 b0, u32 b1) {
    asm volatile(
        "mma.sync.aligned.m16n8k16.row.col.f32.bf16.bf16.f32 "
        "{%0,%1,%2,%3}, {%4,%5,%6,%7}, {%8,%9}, {%0,%1,%2,%3};"
        : "+f"(d[0]), "+f"(d[1]), "+f"(d[2]), "+f"(d[3])
        : "r"(a0), "r"(a1), "r"(a2), "r"(a3), "r"(b0), "r"(b1));
}

__global__ __launch_bounds__(128)
void conv3x3_mma_kernel(const float* __restrict__ x,
                        const float* __restrict__ w,
                        float* __restrict__ out) {
    // stage[row][px][s]: s = cin interleaved, (cin q, q+4) adjacent -> LDS.64
    // gives a thread's (k-lo, k-hi) fragment words. 32B pixel stride,
    // conflict-free across the warp.
    __shared__ u32 stage[INR][INPX][8];

    const int tid  = threadIdx.x;
    const int wid  = tid >> 5;
    const int lane = tid & 31;
    const int gid  = lane >> 2;   // 0..7 : fragment row group / cout
    const int q    = lane & 3;    // 0..3 : k-pair / cin selector

    int x0 = blockIdx.x * TPX; if (x0 > OWW - TPX) x0 = OWW - TPX;
    int y0 = blockIdx.y * TR;  if (y0 > OHH - TR)  y0 = OHH - TR;

    // ---- weight fragments: co = gid, cin = q (+4), hi/lo packed ----
    u32 bm[9][2], bc[9][2];
    #pragma unroll
    for (int i = 0; i < 9; ++i) {
        int ky = i / 3, kx = i % 3;
        #pragma unroll
        for (int h = 0; h < 2; ++h) {
            int cin = q + 4 * h;
            float wv = __ldg(&w[((gid * CIN + cin) * 3 + ky) * 3 + kx]);
            __nv_bfloat16 hb = __float2bfloat16(wv);
            float hf = __bfloat162float(hb);
            __nv_bfloat16 lb = __float2bfloat16(wv - hf);
            u32 hu = __bfloat16_as_ushort(hb);
            u32 lu = __bfloat16_as_ushort(lb);
            bm[i][h] = hu | (hu << 16);   // (w_hi, w_hi)
            bc[i][h] = lu;                // (w_lo, 0)
        }
    }

    // ---- stage inputs: hi/lo split, cin-interleaved ----
    for (int it = tid; it < INR * INPX; it += 128) {
        int b  = it / INPX;
        int xl = it - b * INPX;
        const float* ip = x + (size_t)(y0 + b) * IW + (x0 + xl);
        u32 sv[8];
        #pragma unroll
        for (int c = 0; c < 8; ++c) {
            u32 pk = bf16_hi_lo_pack(__ldg(ip + (size_t)c * CH));
            sv[(c & 3) * 2 + (c >> 2)] = pk;
        }
        uint4* dst = reinterpret_cast<uint4*>(&stage[b][xl][0]);
        dst[0] = make_uint4(sv[0], sv[1], sv[2], sv[3]);
        dst[1] = make_uint4(sv[4], sv[5], sv[6], sv[7]);
    }
    __syncthreads();

    // ---- compute: warp handles output rows y0+2*wid, y0+2*wid+1 ----
    const size_t PL = (size_t)OHH * OWW;
    const int r0 = y0 + 2 * wid;

    #pragma unroll 1
    for (int chunk = 0; chunk < 8; ++chunk) {
        float acc0[4] = {0.f, 0.f, 0.f, 0.f};
        float acc1[4] = {0.f, 0.f, 0.f, 0.f};
        const int px = chunk * 16 + gid;

        #pragma unroll
        for (int ir = 0; ir < 4; ++ir) {               // 4 distinct input rows
            const u32* rowp = &stage[2 * wid + ir][0][0];
            uint2 lo[3], hi[3];
            #pragma unroll
            for (int kx = 0; kx < 3; ++kx) {
                lo[kx] = *reinterpret_cast<const uint2*>(rowp + (px + kx) * 8 + 2 * q);
                hi[kx] = *reinterpret_cast<const uint2*>(rowp + (px + 8 + kx) * 8 + 2 * q);
            }
            if (ir < 3) {                              // row0, ky = ir
                #pragma unroll
                for (int kx = 0; kx < 3; ++kx) {
                    int i = ir * 3 + kx;
                    mma16816(acc0, lo[kx].x, hi[kx].x, lo[kx].y, hi[kx].y, bm[i][0], bm[i][1]);
                    mma16816(acc0, lo[kx].x, hi[kx].x, lo[kx].y, hi[kx].y, bc[i][0], bc[i][1]);
                }
            }
            if (ir >= 1) {                             // row1, ky = ir-1
                #pragma unroll
                for (int kx = 0; kx < 3; ++kx) {
                    int i = (ir - 1) * 3 + kx;
                    mma16816(acc1, lo[kx].x, hi[kx].x, lo[kx].y, hi[kx].y, bm[i][0], bm[i][1]);
                    mma16816(acc1, lo[kx].x, hi[kx].x, lo[kx].y, hi[kx].y, bc[i][0], bc[i][1]);
                }
            }
        }

        // D: [0]=D[gid][2q] [1]=D[gid][2q+1] [2]=D[gid+8][2q] [3]=D[gid+8][2q+1]
        int pix = x0 + px;
        float* op0 = out + (size_t)(2 * q) * PL + (size_t)r0 * OWW + pix;
        op0[0]      = acc0[0];
        op0[PL]     = acc0[1];
        op0[8]      = acc0[2];
        op0[PL + 8] = acc0[3];
        float* op1 = op0 + OWW;
        op1[0]      = acc1[0];
        op1[PL]     = acc1[1];
        op1[8]      = acc1[2];
        op1[PL + 8] = acc1[3];
    }
}

extern "C" void kernel_launch(void* const* d_in, const int* in_sizes, int n_in,
                              void* d_out, int out_size) {
    const float* x = (const float*)d_in[0];   // (8, 2048, 2048) fp32
    const float* w = (const float*)d_in[1];   // (8, 8, 3, 3) fp32
    float* out = (float*)d_out;               // (8, 2046, 2046) fp32

    dim3 grid(16, 256);   // 16 x-tiles x 256 y-tiles (8 rows each), clamped
    conv3x3_mma_kernel<<<grid, 128>>>(x, w, out);
}

// round 7
// speedup vs baseline: 1.0007x; 1.0007x over previous
#include <cuda_runtime.h>
#include <cuda_bf16.h>
#include <cstdint>

// Conv2d 3x3 VALID, C_in=C_out=8, 2048x2048 fp32 -> (8, 2046, 2046)
// Round 7: mma.sync m16n8k16 bf16 hi/lo conv, 2 output rows per warp,
// 4 independent accumulator chains (main/corr x row0/row1) interleaved
// to break dependent-HMMA latency chains.

#define CIN   8
#define COUT  8
#define IH    2048
#define IW    2048
#define OHH   2046
#define OWW   2046
#define CH    (IH*IW)
#define TPX   128
#define TR    8           // output rows per block (2 per warp)
#define INR   10          // TR + 2 input rows staged
#define INPX  130

typedef uint32_t u32;

__device__ __forceinline__ u32 bf16_hi_lo_pack(float v) {
    __nv_bfloat16 hb = __float2bfloat16(v);
    float hf = __bfloat162float(hb);
    __nv_bfloat16 lb = __float2bfloat16(v - hf);
    return (u32)__bfloat16_as_ushort(hb) | ((u32)__bfloat16_as_ushort(lb) << 16);
}

__device__ __forceinline__ void mma16816(float* d,
                                         u32 a0, u32 a1, u32 a2, u32 a3,
                                         u32 b0, u32 b1) {
    asm volatile(
        "mma.sync.aligned.m16n8k16.row.col.f32.bf16.bf16.f32 "
        "{%0,%1,%2,%3}, {%4,%5,%6,%7}, {%8,%9}, {%0,%1,%2,%3};"
        : "+f"(d[0]), "+f"(d[1]), "+f"(d[2]), "+f"(d[3])
        : "r"(a0), "r"(a1), "r"(a2), "r"(a3), "r"(b0), "r"(b1));
}

__global__ __launch_bounds__(128)
void conv3x3_mma_kernel(const float* __restrict__ x,
                        const float* __restrict__ w,
                        float* __restrict__ out) {
    // stage[row][px][s]: s = cin interleaved, (cin q, q+4) adjacent -> one
    // LDS.64 yields a thread's (k-lo, k-hi) fragment words. 32B pixel stride.
    __shared__ u32 stage[INR][INPX][8];

    const int tid  = threadIdx.x;
    const int wid  = tid >> 5;
    const int lane = tid & 31;
    const int gid  = lane >> 2;   // 0..7 : fragment row / cout
    const int q    = lane & 3;    // 0..3 : k-pair / cin selector

    int x0 = blockIdx.x * TPX; if (x0 > OWW - TPX) x0 = OWW - TPX;
    int y0 = blockIdx.y * TR;  if (y0 > OHH - TR)  y0 = OHH - TR;

    // ---- weight fragments: co = gid, cin = q (+4), hi/lo packed ----
    u32 bm[9][2], bc[9][2];
    #pragma unroll
    for (int i = 0; i < 9; ++i) {
        int ky = i / 3, kx = i % 3;
        #pragma unroll
        for (int h = 0; h < 2; ++h) {
            int cin = q + 4 * h;
            float wv = __ldg(&w[((gid * CIN + cin) * 3 + ky) * 3 + kx]);
            __nv_bfloat16 hb = __float2bfloat16(wv);
            float hf = __bfloat162float(hb);
            __nv_bfloat16 lb = __float2bfloat16(wv - hf);
            u32 hu = __bfloat16_as_ushort(hb);
            u32 lu = __bfloat16_as_ushort(lb);
            bm[i][h] = hu | (hu << 16);   // (w_hi, w_hi)
            bc[i][h] = lu;                // (w_lo, 0)
        }
    }

    // ---- stage inputs: hi/lo split, cin-interleaved ----
    for (int it = tid; it < INR * INPX; it += 128) {
        int b  = it / INPX;
        int xl = it - b * INPX;
        const float* ip = x + (size_t)(y0 + b) * IW + (x0 + xl);
        u32 sv[8];
        #pragma unroll
        for (int c = 0; c < 8; ++c) {
            u32 pk = bf16_hi_lo_pack(__ldg(ip + (size_t)c * CH));
            sv[(c & 3) * 2 + (c >> 2)] = pk;
        }
        uint4* dst = reinterpret_cast<uint4*>(&stage[b][xl][0]);
        dst[0] = make_uint4(sv[0], sv[1], sv[2], sv[3]);
        dst[1] = make_uint4(sv[4], sv[5], sv[6], sv[7]);
    }
    __syncthreads();

    // ---- compute: warp handles output rows y0+2*wid, y0+2*wid+1 ----
    const size_t PL = (size_t)OHH * OWW;
    const int r0 = y0 + 2 * wid;

    // per-input-row fragment base pointers (hoisted address math)
    const u32* rbase[4];
    #pragma unroll
    for (int ir = 0; ir < 4; ++ir)
        rbase[ir] = &stage[2 * wid + ir][gid][2 * q];

    #pragma unroll 1
    for (int chunk = 0; chunk < 8; ++chunk) {
        // 4 independent accumulator chains
        float aM0[4] = {0,0,0,0}, aC0[4] = {0,0,0,0};
        float aM1[4] = {0,0,0,0}, aC1[4] = {0,0,0,0};
        const int co = chunk * 16 * 8;   // u32 offset of chunk base pixel

        #pragma unroll
        for (int ir = 0; ir < 4; ++ir) {               // 4 distinct input rows
            const u32* rp = rbase[ir] + co;
            uint2 lo[3], hi[3];
            #pragma unroll
            for (int kx = 0; kx < 3; ++kx) {
                lo[kx] = *reinterpret_cast<const uint2*>(rp + kx * 8);
                hi[kx] = *reinterpret_cast<const uint2*>(rp + (kx + 8) * 8);
            }
            // Interleave across the 4 chains: consecutive HMMAs independent.
            #pragma unroll
            for (int kx = 0; kx < 3; ++kx) {
                const int i0 = ir * 3 + kx;        // row0 tap (ky = ir)
                const int i1 = (ir - 1) * 3 + kx;  // row1 tap (ky = ir-1)
                u32 f0 = lo[kx].x, f1 = hi[kx].x, f2 = lo[kx].y, f3 = hi[kx].y;
                if (ir < 3)  mma16816(aM0, f0, f1, f2, f3, bm[i0][0], bm[i0][1]);
                if (ir >= 1) mma16816(aM1, f0, f1, f2, f3, bm[i1][0], bm[i1][1]);
                if (ir < 3)  mma16816(aC0, f0, f1, f2, f3, bc[i0][0], bc[i0][1]);
                if (ir >= 1) mma16816(aC1, f0, f1, f2, f3, bc[i1][0], bc[i1][1]);
            }
        }

        // D: [0]=D[gid][2q] [1]=D[gid][2q+1] [2]=D[gid+8][2q] [3]=D[gid+8][2q+1]
        int pix = x0 + chunk * 16 + gid;
        float* op0 = out + (size_t)(2 * q) * PL + (size_t)r0 * OWW + pix;
        op0[0]      = aM0[0] + aC0[0];
        op0[PL]     = aM0[1] + aC0[1];
        op0[8]      = aM0[2] + aC0[2];
        op0[PL + 8] = aM0[3] + aC0[3];
        float* op1 = op0 + OWW;
        op1[0]      = aM1[0] + aC1[0];
        op1[PL]     = aM1[1] + aC1[1];
        op1[8]      = aM1[2] + aC1[2];
        op1[PL + 8] = aM1[3] + aC1[3];
    }
}

extern "C" void kernel_launch(void* const* d_in, const int* in_sizes, int n_in,
                              void* d_out, int out_size) {
    const float* x = (const float*)d_in[0];   // (8, 2048, 2048) fp32
    const float* w = (const float*)d_in[1];   // (8, 8, 3, 3) fp32
    float* out = (float*)d_out;               // (8, 2046, 2046) fp32

    dim3 grid(16, 256);   // 16 x-tiles x 256 y-tiles (8 rows each), clamped
    conv3x3_mma_kernel<<<grid, 128>>>(x, w, out);
}